// round 4
// baseline (speedup 1.0000x reference)
#include <cuda_runtime.h>
#include <cuda_bf16.h>
#include <cstdint>

// Problem constants
#define NCLS   100
#define DDIM   10000
#define NROW   16384
#define MC     128          // rows per CTA
#define NC     112          // classes padded for 14 n8-tiles
#define KC     64           // K chunk (bf16), 128B rows -> full XOR swizzle
#define NCH    157          // ceil(10000/64)
#define KPAD   (NCH * KC)   // 10048
#define RPARTS 8
#define CC     32           // accum column chunk (static smem)
#define CCH2   313          // ceil(10000/32)

// ---------------- device scratch ----------------
__device__ __nv_bfloat16 g_Bhi[NC * KPAD];
__device__ __nv_bfloat16 g_Blo[NC * KPAD];
__device__ int   g_flagpred[NROW];
__device__ int   g_tgt[NROW];          // canonicalized int32 targets
__device__ int   g_is64;               // 1 if targets buffer is int64-laid-out
__device__ float g_part[RPARTS * 2 * NCLS * DDIM];

// ---------------- smem layout (gemm) ----------------
#define GEMM_SMEM 122880

// ---------------- asm helpers (base compute_103 features only) ----------------
__device__ __forceinline__ uint32_t cvta_s(const void* p) {
    uint32_t a;
    asm("{ .reg .u64 t; cvta.to.shared.u64 t, %1; cvt.u32.u64 %0, t; }" : "=r"(a) : "l"(p));
    return a;
}
__device__ __forceinline__ void ldsm4(uint32_t* r, uint32_t a) {
    asm volatile("ldmatrix.sync.aligned.m8n8.x4.shared.b16 {%0,%1,%2,%3}, [%4];"
                 : "=r"(r[0]), "=r"(r[1]), "=r"(r[2]), "=r"(r[3]) : "r"(a));
}
__device__ __forceinline__ void ldsm2(uint32_t* r, uint32_t a) {
    asm volatile("ldmatrix.sync.aligned.m8n8.x2.shared.b16 {%0,%1}, [%2];"
                 : "=r"(r[0]), "=r"(r[1]) : "r"(a));
}
__device__ __forceinline__ void mma16816(float* d, const uint32_t* a, const uint32_t* b) {
    asm volatile(
        "mma.sync.aligned.m16n8k16.row.col.f32.bf16.bf16.f32 "
        "{%0,%1,%2,%3}, {%4,%5,%6,%7}, {%8,%9}, {%0,%1,%2,%3};"
        : "+f"(d[0]), "+f"(d[1]), "+f"(d[2]), "+f"(d[3])
        : "r"(a[0]), "r"(a[1]), "r"(a[2]), "r"(a[3]), "r"(b[0]), "r"(b[1]));
}
__device__ __forceinline__ void cpasync16(uint32_t dst, const void* src) {
    asm volatile("cp.async.cg.shared.global [%0], [%1], 16;" :: "r"(dst), "l"(src));
}
__device__ __forceinline__ void cp_commit() { asm volatile("cp.async.commit_group;"); }
__device__ __forceinline__ void cp_wait0()  { asm volatile("cp.async.wait_group 0;"); }

__device__ __forceinline__ uint2 split_pack(float4 f, uint2& lo) {
    __nv_bfloat162 h01 = __floats2bfloat162_rn(f.x, f.y);
    __nv_bfloat162 h23 = __floats2bfloat162_rn(f.z, f.w);
    __nv_bfloat162 l01 = __floats2bfloat162_rn(f.x - __low2float(h01), f.y - __high2float(h01));
    __nv_bfloat162 l23 = __floats2bfloat162_rn(f.z - __low2float(h23), f.w - __high2float(h23));
    uint2 hi;
    hi.x = *reinterpret_cast<uint32_t*>(&h01);
    hi.y = *reinterpret_cast<uint32_t*>(&h23);
    lo.x = *reinterpret_cast<uint32_t*>(&l01);
    lo.y = *reinterpret_cast<uint32_t*>(&l23);
    return hi;
}

// ================= kernel 0a: detect targets dtype layout =================
// If targets are int64 (little-endian, values 0..99), every odd int32 slot is 0.
// Probability of a false positive with genuine int32 targets: ~(1/100)^256 = 0.
__global__ void detect_tgt_kernel(const int* __restrict__ t32) {
    __shared__ int any_nonzero;
    if (threadIdx.x == 0) any_nonzero = 0;
    __syncthreads();
    const int v = t32[2 * threadIdx.x + 1];      // odd slots of first 256 pairs
    if (v != 0) atomicOr(&any_nonzero, 1);
    __syncthreads();
    if (threadIdx.x == 0) g_is64 = any_nonzero ? 0 : 1;
}

// ================= kernel 0b: canonicalize targets to int32 =================
__global__ void conv_tgt_kernel(const int* __restrict__ t32) {
    const int i = blockIdx.x * blockDim.x + threadIdx.x;
    if (i < NROW) g_tgt[i] = g_is64 ? t32[2 * i] : t32[i];
}

// ================= kernel 1: split class_hvs into bf16 hi/lo (zero-padded) =========
__global__ void prep_b_kernel(const float* __restrict__ ch) {
    int idx = blockIdx.x * blockDim.x + threadIdx.x;
    if (idx >= NC * KPAD) return;
    int row = idx / KPAD, col = idx - row * KPAD;
    float v = (row < NCLS && col < DDIM) ? ch[row * DDIM + col] : 0.0f;
    __nv_bfloat16 hi = __float2bfloat16_rn(v);
    g_Bhi[idx] = hi;
    g_Blo[idx] = __float2bfloat16_rn(v - __bfloat162float(hi));
}

// ================= kernel 2: split-bf16 3-GEMM via mma.sync + argmax epilogue =======
__global__ __launch_bounds__(256, 1)
void gemm_kernel(const float* __restrict__ enc,
                 float* __restrict__ out_scores) {
    extern __shared__ __align__(128) char smem[];
    const uint32_t sb = cvta_s(smem);
    const int tid = threadIdx.x, lane = tid & 31, wid = tid >> 5;
    const int warpM = wid >> 1, warpN = wid & 1;   // 4 x 2 warp grid
    const int r0 = blockIdx.x * MC;

    // ---- ldmatrix offsets (tile-relative, stage-independent) ----
    uint32_t aoff[2][4];
    #pragma unroll
    for (int mi = 0; mi < 2; mi++) {
        const int row = warpM * 32 + mi * 16 + (lane & 15);
        const int cl = lane >> 4;
        #pragma unroll
        for (int ks = 0; ks < 4; ks++)
            aoff[mi][ks] = row * 128 + (((ks * 2 + cl) ^ (row & 7)) * 16);
    }
    uint32_t boff[3][4], b2off[4];
    #pragma unroll
    for (int t = 0; t < 3; t++) {
        const int row = warpN * 56 + t * 16 + (lane & 7) + ((lane >> 4) & 1) * 8;
        const int cl = (lane >> 3) & 1;
        #pragma unroll
        for (int ks = 0; ks < 4; ks++)
            boff[t][ks] = row * 128 + (((ks * 2 + cl) ^ (row & 7)) * 16);
    }
    {
        const int row = warpN * 56 + 48 + (lane & 7);
        const int cl = (lane >> 3) & 1;
        #pragma unroll
        for (int ks = 0; ks < 4; ks++)
            b2off[ks] = row * 128 + (((ks * 2 + cl) ^ (row & 7)) * 16);
    }

    // ---- A global-load / smem-store mapping ----
    const int aRow = tid >> 1;
    const int aCol0 = (tid & 1) * 32;
    const float* aptr = enc + (size_t)(r0 + aRow) * DDIM + aCol0;
    uint32_t asw[8];
    #pragma unroll
    for (int j = 0; j < 8; j++) {
        const int byte = aCol0 * 2 + j * 8;
        asw[j] = aRow * 128 + (byte ^ ((aRow & 7) << 4));
    }

    // ---- B cp.async mapping: 7 16B chunks per thread ----
    const __nv_bfloat16* bsrc[7];
    uint32_t bdstrel[7];
    #pragma unroll
    for (int q = 0; q < 7; q++) {
        const int cid = tid + q * 256;
        const int half = cid / 896;
        const int rem = cid - half * 896;
        const int brow = rem >> 3, bc = rem & 7;
        bsrc[q] = (half ? g_Blo : g_Bhi) + (size_t)brow * KPAD + bc * 8;
        bdstrel[q] = half * 14336 + brow * 128 + ((bc ^ (brow & 7)) * 16);
    }

    float d[2][7][4];
    #pragma unroll
    for (int mi = 0; mi < 2; mi++)
        #pragma unroll
        for (int ni = 0; ni < 7; ni++)
            #pragma unroll
            for (int r = 0; r < 4; r++) d[mi][ni][r] = 0.0f;

    float4 pf[8];

    // ---- prologue: chunk 0 into stage 0 ----
    #pragma unroll
    for (int j = 0; j < 8; j++) {
        const int gcol = aCol0 + j * 4;
        pf[j] = (gcol < DDIM) ? *(const float4*)(aptr + j * 4)
                              : make_float4(0.f, 0.f, 0.f, 0.f);
    }
    #pragma unroll
    for (int j = 0; j < 8; j++) {
        uint2 lo; uint2 hi = split_pack(pf[j], lo);
        *(uint2*)(smem + asw[j]) = hi;
        *(uint2*)(smem + 16384 + asw[j]) = lo;
    }
    #pragma unroll
    for (int q = 0; q < 7; q++)
        cpasync16(sb + 65536 + bdstrel[q], bsrc[q]);
    cp_commit();
    cp_wait0();
    __syncthreads();

    // ---- main pipelined loop ----
    for (int i = 0; i < NCH; i++) {
        const int s = i & 1;
        if (i + 1 < NCH) {
            const int k0 = (i + 1) * KC;
            #pragma unroll
            for (int j = 0; j < 8; j++) {
                const int gcol = k0 + aCol0 + j * 4;
                pf[j] = (gcol < DDIM) ? *(const float4*)(aptr + k0 + j * 4)
                                      : make_float4(0.f, 0.f, 0.f, 0.f);
            }
            const uint32_t bb = sb + 65536 + (s ^ 1) * 28672;
            #pragma unroll
            for (int q = 0; q < 7; q++)
                cpasync16(bb + bdstrel[q], bsrc[q] + k0);
            cp_commit();
        }

        const uint32_t abase = sb + s * 32768;
        const uint32_t bbase = sb + 65536 + s * 28672;
        #pragma unroll
        for (int ks = 0; ks < 4; ks++) {
            uint32_t ah[2][4], al[2][4], bh[7][2], bl[7][2];
            ldsm4(ah[0], abase + aoff[0][ks]);
            ldsm4(ah[1], abase + aoff[1][ks]);
            ldsm4(al[0], abase + 16384 + aoff[0][ks]);
            ldsm4(al[1], abase + 16384 + aoff[1][ks]);
            #pragma unroll
            for (int t = 0; t < 3; t++) {
                ldsm4(&bh[2 * t][0], bbase + boff[t][ks]);
                ldsm4(&bl[2 * t][0], bbase + 14336 + boff[t][ks]);
            }
            ldsm2(bh[6], bbase + b2off[ks]);
            ldsm2(bl[6], bbase + 14336 + b2off[ks]);

            #pragma unroll
            for (int mi = 0; mi < 2; mi++)
                #pragma unroll
                for (int ni = 0; ni < 7; ni++) {
                    mma16816(d[mi][ni], ah[mi], bh[ni]);
                    mma16816(d[mi][ni], ah[mi], bl[ni]);
                    mma16816(d[mi][ni], al[mi], bh[ni]);
                }
        }

        if (i + 1 < NCH) {
            const int s2 = (s ^ 1) * 32768;
            #pragma unroll
            for (int j = 0; j < 8; j++) {
                uint2 lo; uint2 hi = split_pack(pf[j], lo);
                *(uint2*)(smem + s2 + asw[j]) = hi;
                *(uint2*)(smem + s2 + 16384 + asw[j]) = lo;
            }
            cp_wait0();
        }
        __syncthreads();
    }

    // ---- epilogue: accums -> smem tile (stride 113), scores + argmax ----
    float* tile = (float*)smem;
    #pragma unroll
    for (int mi = 0; mi < 2; mi++)
        #pragma unroll
        for (int ni = 0; ni < 7; ni++)
            #pragma unroll
            for (int r = 0; r < 4; r++) {
                const int row = warpM * 32 + mi * 16 + (lane >> 2) + (r >= 2 ? 8 : 0);
                const int col = warpN * 56 + ni * 8 + (lane & 3) * 2 + (r & 1);
                tile[row * 113 + col] = d[mi][ni][r];
            }
    __syncthreads();

    for (int idx = tid; idx < MC * NCLS; idx += 256) {
        const int r = idx / NCLS, c = idx - r * NCLS;
        out_scores[(size_t)(r0 + r) * NCLS + c] = tile[r * 113 + c];
    }
    if (tid < MC) {
        const int r = tid;
        float best = tile[r * 113];
        int bi = 0;
        #pragma unroll 4
        for (int c = 1; c < NCLS; c++) {
            const float v = tile[r * 113 + c];
            if (v > best) { best = v; bi = c; }
        }
        g_flagpred[r0 + r] = (g_tgt[r0 + r] != bi) ? bi : -1;
    }
}

// ================= kernel 3: masked segment sums (static smem) ==========
// 64 threads = 2 warps: warp 0 accumulates the add-array (keyed by target),
// warp 1 the sub-array (keyed by pred). Each (role, cls, col) has one owner.
__global__ __launch_bounds__(64)
void accum_kernel(const float* __restrict__ enc) {
    __shared__ float acc[2][NCLS][CC];     // 25600 B, static
    const int t = threadIdx.x;
    const int col = t & (CC - 1);
    const int role = t >> 5;               // 0 = add (target), 1 = sub (pred)

    for (int i = t; i < 2 * NCLS * CC; i += 64) ((float*)acc)[i] = 0.0f;
    __syncthreads();

    const int c0 = blockIdx.x * CC;
    const bool colOK = (c0 + col) < DDIM;
    const int rcnt = NROW / RPARTS;
    const int rbeg = blockIdx.y * rcnt;

    for (int r = rbeg; r < rbeg + rcnt; r += 8) {
        int fp[8]; int tg[8]; float v[8];
        #pragma unroll
        for (int u = 0; u < 8; u++) fp[u] = g_flagpred[r + u];
        #pragma unroll
        for (int u = 0; u < 8; u++) tg[u] = g_tgt[r + u];
        #pragma unroll
        for (int u = 0; u < 8; u++)
            v[u] = (fp[u] >= 0 && colOK)
                     ? __ldg(enc + (size_t)(r + u) * DDIM + c0 + col) : 0.0f;
        #pragma unroll
        for (int u = 0; u < 8; u++) {
            if (fp[u] >= 0) {
                const int cls = role ? fp[u] : tg[u];
                acc[role][cls][col] += v[u];
            }
        }
    }
    __syncthreads();

    if (colOK) {
        const size_t base = (size_t)blockIdx.y * 2 * NCLS * DDIM
                          + (size_t)role * NCLS * DDIM + c0 + col;
        #pragma unroll 4
        for (int cls = 0; cls < NCLS; cls++)
            g_part[base + (size_t)cls * DDIM] = acc[role][cls][col];
    }
}

// ================= kernel 4: reduce partials, clip, update =================
__global__ void finalize_kernel(const float* __restrict__ ch, float* __restrict__ out2) {
    int i = blockIdx.x * blockDim.x + threadIdx.x;
    if (i >= NCLS * DDIM) return;
    float a = 0.0f, s = 0.0f;
    #pragma unroll
    for (int p = 0; p < RPARTS; p++) {
        a += g_part[((size_t)p * 2 + 0) * NCLS * DDIM + i];
        s += g_part[((size_t)p * 2 + 1) * NCLS * DDIM + i];
    }
    a = fminf(fmaxf(a, -1.0f), 1.0f);
    s = fminf(fmaxf(s, -1.0f), 1.0f);
    out2[i] = ch[i] + a - s;
}

// ================= launch =================
extern "C" void kernel_launch(void* const* d_in, const int* in_sizes, int n_in,
                              void* d_out, int out_size) {
    (void)in_sizes; (void)n_in; (void)out_size;
    const float* enc = (const float*)d_in[0];
    const int* tgt32 = (const int*)d_in[1];
    const float* ch = (const float*)d_in[2];
    float* out = (float*)d_out;
    float* out_scores = out;                       // [N, NCLS]
    float* out_hvs = out + (size_t)NROW * NCLS;    // [NCLS, DDIM]

    cudaFuncSetAttribute(gemm_kernel, cudaFuncAttributeMaxDynamicSharedMemorySize, GEMM_SMEM);

    detect_tgt_kernel<<<1, 256>>>(tgt32);
    conv_tgt_kernel<<<(NROW + 255) / 256, 256>>>(tgt32);
    prep_b_kernel<<<(NC * KPAD + 255) / 256, 256>>>(ch);
    gemm_kernel<<<NROW / MC, 256, GEMM_SMEM>>>(enc, out_scores);
    accum_kernel<<<dim3(CCH2, RPARTS), 64>>>(enc);
    finalize_kernel<<<(NCLS * DDIM + 255) / 256, 256>>>(ch, out_hvs);
}